// round 3
// baseline (speedup 1.0000x reference)
#include <cuda_runtime.h>
#include <math.h>

#define T_LEN     1048576
#define MAXO      25
#define CLAMP_HI  24.0f
#define SEG       8
#define NTHREADS  256
#define PER_BLOCK (SEG*NTHREADS)     /* 2048 */
#define NB        (T_LEN/PER_BLOCK)  /* 512  */

struct Fn { float a, b, c; };

__device__ Fn    g_blockF[NB];
__device__ float g_blockStart[NB];

__device__ __forceinline__ Fn fn_identity() { return Fn{0.f, -1e30f, 1e30f}; }

// f1 applied first, then f2:  (f2 o f1)(x) = min(max(x+a, b), c)
__device__ __forceinline__ Fn fn_compose(Fn f1, Fn f2) {
    Fn r;
    r.a = f1.a + f2.a;
    r.b = fmaxf(f1.b + f2.a, f2.b);
    r.c = fminf(fmaxf(f1.c + f2.a, f2.b), f2.c);
    return r;
}

__device__ __forceinline__ float fn_apply(Fn f, float x) {
    return fminf(fmaxf(x + f.a, f.b), f.c);
}

__device__ __forceinline__ Fn warp_incl_scan(Fn v, int lane) {
    #pragma unroll
    for (int off = 1; off < 32; off <<= 1) {
        float pa = __shfl_up_sync(0xffffffffu, v.a, off);
        float pb = __shfl_up_sync(0xffffffffu, v.b, off);
        float pc = __shfl_up_sync(0xffffffffu, v.c, off);
        if (lane >= off) v = fn_compose(Fn{pa, pb, pc}, v);
    }
    return v;
}

// ---------------------------------------------------------------------------
// K1: per-block composed clamp function
// ---------------------------------------------------------------------------
__global__ void __launch_bounds__(NTHREADS)
k1_block_totals(const int* __restrict__ seq, const float* __restrict__ delta) {
    __shared__ float dl[16];
    __shared__ Fn warpTot[NTHREADS / 32];
    int tid = threadIdx.x, lane = tid & 31, wid = tid >> 5;
    if (tid < 16) dl[tid] = delta[tid];
    __syncthreads();

    const int4* p = (const int4*)(seq + (size_t)blockIdx.x * PER_BLOCK + tid * SEG);
    int4 v0 = p[0], v1 = p[1];
    int vals[8] = {v0.x, v0.y, v0.z, v0.w, v1.x, v1.y, v1.z, v1.w};

    Fn f = fn_identity();
    #pragma unroll
    for (int i = 0; i < 8; i++) {
        float d = dl[vals[i]];
        f.a += d;
        f.b = fmaxf(f.b + d, 0.f);
        f.c = fminf(fmaxf(f.c + d, 0.f), CLAMP_HI);
    }
    Fn inc = warp_incl_scan(f, lane);
    if (lane == 31) warpTot[wid] = inc;
    __syncthreads();
    if (tid == 0) {
        Fn t = warpTot[0];
        #pragma unroll
        for (int w = 1; w < NTHREADS / 32; w++) t = fn_compose(t, warpTot[w]);
        g_blockF[blockIdx.x] = t;
    }
}

// ---------------------------------------------------------------------------
// K2: scan the NB=512 block functions -> per-block start counter value
// ---------------------------------------------------------------------------
__global__ void __launch_bounds__(NB)
k2_scan_blocks() {
    __shared__ Fn warpTot[NB / 32];   // 16
    int tid = threadIdx.x, lane = tid & 31, wid = tid >> 5;
    Fn f = g_blockF[tid];
    Fn inc = warp_incl_scan(f, lane);
    if (lane == 31) warpTot[wid] = inc;
    __syncthreads();
    if (wid == 0) {
        Fn v = (lane < NB / 32) ? warpTot[lane] : fn_identity();
        #pragma unroll
        for (int off = 1; off < NB / 32; off <<= 1) {
            float pa = __shfl_up_sync(0xffffffffu, v.a, off);
            float pb = __shfl_up_sync(0xffffffffu, v.b, off);
            float pc = __shfl_up_sync(0xffffffffu, v.c, off);
            if (lane >= off) v = fn_compose(Fn{pa, pb, pc}, v);
        }
        if (lane < NB / 32) warpTot[lane] = v;
    }
    __syncthreads();
    float pa = __shfl_up_sync(0xffffffffu, inc.a, 1);
    float pb = __shfl_up_sync(0xffffffffu, inc.b, 1);
    float pc = __shfl_up_sync(0xffffffffu, inc.c, 1);
    Fn lane_excl = (lane == 0) ? fn_identity() : Fn{pa, pb, pc};
    Fn wexcl     = (wid  == 0) ? fn_identity() : warpTot[wid - 1];
    Fn excl = fn_compose(wexcl, lane_excl);
    g_blockStart[tid] = fn_apply(excl, 0.f);
}

// ---------------------------------------------------------------------------
// K3: counters (exact local sequential recurrence) + factored softmax,
//     staged in SMEM for fully coalesced float4 output writes.
// ---------------------------------------------------------------------------
__global__ void __launch_bounds__(NTHREADS)
k3_output(const int* __restrict__ seq, const float* __restrict__ delta,
          const float* __restrict__ bias, const float* __restrict__ scale,
          float* __restrict__ out) {
    __shared__ float dl[16];
    __shared__ float An[MAXO], Ap[MAXO];
    __shared__ Fn    warpTot[NTHREADS / 32];
    __shared__ __align__(16) float cnt[NTHREADS * (SEG + 1)];  // stride 9: conflict-free
    __shared__ __align__(16) float stage[NTHREADS * MAXO];     // 6400 floats = 25.6 KB

    int tid = threadIdx.x, lane = tid & 31, wid = tid >> 5;
    float s = scale[0];
    if (tid < 16) dl[tid] = delta[tid];
    if (tid < MAXO) {
        float fj = (float)tid;
        An[tid] = expf(bias[tid] - s * fj);   // used when j >= c  (* e^{ s c})
        Ap[tid] = expf(bias[tid] + s * fj);   // used when j <  c  (* e^{-s c})
    }
    __syncthreads();

    const int4* p = (const int4*)(seq + (size_t)blockIdx.x * PER_BLOCK + tid * SEG);
    int4 v0 = p[0], v1 = p[1];
    int vals[8] = {v0.x, v0.y, v0.z, v0.w, v1.x, v1.y, v1.z, v1.w};
    float dv[8];

    Fn f = fn_identity();
    #pragma unroll
    for (int i = 0; i < 8; i++) {
        float d = dl[vals[i]];
        dv[i] = d;
        f.a += d;
        f.b = fmaxf(f.b + d, 0.f);
        f.c = fminf(fmaxf(f.c + d, 0.f), CLAMP_HI);
    }

    // block exclusive scan of thread functions
    Fn inc = warp_incl_scan(f, lane);
    if (lane == 31) warpTot[wid] = inc;
    __syncthreads();
    if (wid == 0) {
        Fn v = (lane < NTHREADS / 32) ? warpTot[lane] : fn_identity();
        #pragma unroll
        for (int off = 1; off < NTHREADS / 32; off <<= 1) {
            float pa = __shfl_up_sync(0xffffffffu, v.a, off);
            float pb = __shfl_up_sync(0xffffffffu, v.b, off);
            float pc = __shfl_up_sync(0xffffffffu, v.c, off);
            if (lane >= off) v = fn_compose(Fn{pa, pb, pc}, v);
        }
        if (lane < NTHREADS / 32) warpTot[lane] = v;
    }
    __syncthreads();
    float pa = __shfl_up_sync(0xffffffffu, inc.a, 1);
    float pb = __shfl_up_sync(0xffffffffu, inc.b, 1);
    float pc = __shfl_up_sync(0xffffffffu, inc.c, 1);
    Fn lane_excl = (lane == 0) ? fn_identity() : Fn{pa, pb, pc};
    Fn wexcl     = (wid  == 0) ? fn_identity() : warpTot[wid - 1];
    Fn excl = fn_compose(wexcl, lane_excl);

    // exact sequential recurrence within this thread's 8-element segment
    float c = fn_apply(excl, g_blockStart[blockIdx.x]);
    #pragma unroll
    for (int i = 0; i < 8; i++) {
        c = fminf(fmaxf(c + dv[i], 0.f), CLAMP_HI);
        cnt[tid * (SEG + 1) + i] = c;
    }
    __syncthreads();

    // softmax in tiles of 256 rows; stage then coalesced float4 copy out
    for (int tile = 0; tile < PER_BLOCK / NTHREADS; tile++) {
        int r = tile * NTHREADS + tid;
        float cc  = cnt[(r >> 3) * (SEG + 1) + (r & 7)];
        float ec  = expf(s * cc);
        float emc = expf(-s * cc);
        float w[MAXO];
        float sum = 0.f;
        #pragma unroll
        for (int j = 0; j < MAXO; j++) {
            float wj = ((float)j >= cc) ? An[j] * ec : Ap[j] * emc;
            w[j] = wj;
            sum += wj;
        }
        float inv = 1.0f / sum;
        #pragma unroll
        for (int j = 0; j < MAXO; j++) stage[tid * MAXO + j] = w[j] * inv;
        __syncthreads();

        const float4* ss = (const float4*)stage;
        float4* dd = (float4*)(out + ((size_t)blockIdx.x * PER_BLOCK + tile * NTHREADS) * (size_t)MAXO);
        for (int k = tid; k < NTHREADS * MAXO / 4; k += NTHREADS) dd[k] = ss[k];
        __syncthreads();
    }
}

// ---------------------------------------------------------------------------
extern "C" void kernel_launch(void* const* d_in, const int* in_sizes, int n_in,
                              void* d_out, int out_size) {
    const int*   seq   = (const int*)  d_in[0];
    const float* delta = (const float*)d_in[1];
    const float* bias  = (const float*)d_in[2];
    const float* scale = (const float*)d_in[3];
    float* out = (float*)d_out;

    k1_block_totals<<<NB, NTHREADS>>>(seq, delta);
    k2_scan_blocks<<<1, NB>>>();
    k3_output<<<NB, NTHREADS>>>(seq, delta, bias, scale, out);
}